// round 3
// baseline (speedup 1.0000x reference)
#include <cuda_runtime.h>
#include <math.h>

// CharsLstm: B=64, T=512, E=256, H=1024, V=256.
// Inputs (metadata order): x[B,T] int32, emb[V,E], W_ih[4H,E], W_hh[4H,H],
//                          b_ih[4H], b_hh[4H], h0[B,H], c0[B,H]  (all fp32)
// Output: final h [B,H] fp32.
//
// Strategy R2 (fp32 baseline, capture-hardened):
//  1) table[v][g] = dot(emb[v], W_ih[g]) + b_ih[g] + b_hh[g]   (v==0 -> bias only,
//     replicating padding_idx=0). Input projection becomes a gather.
//  2) 512 sequential step kernels (kernel boundary = grid sync). Each step:
//     gates = h_prev @ W_hh^T  (fp32, smem-tiled), then fused LSTM cell with
//     table gather, c updated in place, h ping-pong selected DEVICE-SIDE
//     (no cudaGetSymbolAddress in the capture path); last step writes d_out.

#define BB 64
#define TT 512
#define EE 256
#define HH 1024
#define GG 4096          // 4*H
#define JT 8             // hidden units per block
#define KT 32            // k-tile
#define NBLK 128         // HH / JT
#define WPITCH 36        // padded pitch for w_s[k][row]
#define HPITCH 68        // padded pitch for h_s[k][b]
#define GPITCH 65

__device__ float g_table[256 * GG];     // 4 MB
__device__ float g_h[2][BB * HH];       // ping-pong hidden state
__device__ float g_c[BB * HH];          // cell state (in place)

// ---------------------------------------------------------------------------
// table[v][g] = (v==0 ? 0 : dot(emb[v,:], W_ih[g,:])) + b_ih[g] + b_hh[g]
// grid: (GG/128, 256), block: 128 threads, one g per thread
// ---------------------------------------------------------------------------
__global__ void table_kernel(const float* __restrict__ emb,
                             const float* __restrict__ W_ih,
                             const float* __restrict__ b_ih,
                             const float* __restrict__ b_hh) {
    __shared__ float es[EE];
    const int v = blockIdx.y;
    const int g = blockIdx.x * 128 + threadIdx.x;
    for (int i = threadIdx.x; i < EE; i += 128) es[i] = emb[v * EE + i];
    __syncthreads();
    float acc = 0.f;
    if (v != 0) {
        const float* wr = W_ih + (size_t)g * EE;
#pragma unroll 8
        for (int e = 0; e < EE; e++) acc += wr[e] * es[e];
    }
    g_table[v * GG + g] = acc + b_ih[g] + b_hh[g];
}

__global__ void initc_kernel(const float* __restrict__ c0) {
    int i = blockIdx.x * 256 + threadIdx.x;
    g_c[i] = c0[i];
}

// ---------------------------------------------------------------------------
// One LSTM timestep.
// Block: 8 hidden units (32 gate rows x 64 batches = 2048 accumulators).
// 256 threads = 2 teams of 128; team 0 handles k in [0,512), team 1 [512,1024);
// partials reduced through smem. Thread tile: 4 rows x 4 batches.
// hprev/hnext resolved device-side from g_h / h0 / out based on t.
// ---------------------------------------------------------------------------
__global__ void __launch_bounds__(256, 1)
step_kernel(const float* __restrict__ Whh,
            const int*   __restrict__ x,
            const float* __restrict__ h0,
            float*       __restrict__ out,
            int t) {
    __shared__ float smem[2 * KT * WPITCH + 2 * KT * HPITCH + 32 * GPITCH];

    const float* __restrict__ hprev = (t == 0) ? h0 : g_h[(t - 1) & 1];
    float* __restrict__ hnext = (t == TT - 1) ? out : g_h[t & 1];

    const int tid  = threadIdx.x;
    const int team = tid >> 7;        // 0 or 1
    const int ttid = tid & 127;
    const int j0   = blockIdx.x * JT;

    float* ws = smem + team * (KT * WPITCH);
    float* hs = smem + 2 * KT * WPITCH + team * (KT * HPITCH);
    float* gs = smem + 2 * KT * WPITCH + 2 * KT * HPITCH;

    // thread tile: rows r0..r0+3 (within gates), batches b0..b0+3
    const int rg = ttid >> 4;         // 0..7
    const int bg = ttid & 15;         // 0..15
    const int r0 = rg * 4;
    const int b0 = bg * 4;

    float a00=0,a01=0,a02=0,a03=0, a10=0,a11=0,a12=0,a13=0;
    float a20=0,a21=0,a22=0,a23=0, a30=0,a31=0,a32=0,a33=0;

    const int kstart = team * (HH / 2);

    // load-index precompute
    const int lr   = ttid >> 2;                               // 0..31 local row
    const int grow = (lr >> 3) * HH + j0 + (lr & 7);          // global W row
    const int wko  = (ttid & 3) * 8;                          // 8 k per thread
    const int lb   = ttid >> 1;                               // 0..63 batch
    const int hko  = (ttid & 1) * 16;                         // 16 k per thread

    for (int tile = 0; tile < (HH / 2) / KT; ++tile) {
        const int k0 = kstart + tile * KT;
        __syncthreads();
        // ---- load W tile (32 rows x KT), transposed into ws[k][row] ----
        {
            const float* src = Whh + (size_t)grow * HH + k0 + wko;
#pragma unroll
            for (int u = 0; u < 2; u++) {
                float4 v = *(const float4*)(src + u * 4);
                int kk = wko + u * 4;
                ws[(kk + 0) * WPITCH + lr] = v.x;
                ws[(kk + 1) * WPITCH + lr] = v.y;
                ws[(kk + 2) * WPITCH + lr] = v.z;
                ws[(kk + 3) * WPITCH + lr] = v.w;
            }
        }
        // ---- load h tile (64 b x KT), transposed into hs[k][b] ----
        {
            const float* src = hprev + (size_t)lb * HH + k0 + hko;
#pragma unroll
            for (int u = 0; u < 4; u++) {
                float4 v = *(const float4*)(src + u * 4);
                int kk = hko + u * 4;
                hs[(kk + 0) * HPITCH + lb] = v.x;
                hs[(kk + 1) * HPITCH + lb] = v.y;
                hs[(kk + 2) * HPITCH + lb] = v.z;
                hs[(kk + 3) * HPITCH + lb] = v.w;
            }
        }
        __syncthreads();
        // ---- compute: 16 FMA per k per thread ----
#pragma unroll 8
        for (int kk = 0; kk < KT; kk++) {
            float4 wv = *(const float4*)(ws + kk * WPITCH + r0);
            float4 hv = *(const float4*)(hs + kk * HPITCH + b0);
            a00 += wv.x * hv.x; a01 += wv.x * hv.y; a02 += wv.x * hv.z; a03 += wv.x * hv.w;
            a10 += wv.y * hv.x; a11 += wv.y * hv.y; a12 += wv.y * hv.z; a13 += wv.y * hv.w;
            a20 += wv.z * hv.x; a21 += wv.z * hv.y; a22 += wv.z * hv.z; a23 += wv.z * hv.w;
            a30 += wv.w * hv.x; a31 += wv.w * hv.y; a32 += wv.w * hv.z; a33 += wv.w * hv.w;
        }
    }

    // ---- cross-team reduction into gs[row][b] ----
    __syncthreads();
    if (team == 1) {
        gs[(r0+0)*GPITCH + b0+0] = a00; gs[(r0+0)*GPITCH + b0+1] = a01;
        gs[(r0+0)*GPITCH + b0+2] = a02; gs[(r0+0)*GPITCH + b0+3] = a03;
        gs[(r0+1)*GPITCH + b0+0] = a10; gs[(r0+1)*GPITCH + b0+1] = a11;
        gs[(r0+1)*GPITCH + b0+2] = a12; gs[(r0+1)*GPITCH + b0+3] = a13;
        gs[(r0+2)*GPITCH + b0+0] = a20; gs[(r0+2)*GPITCH + b0+1] = a21;
        gs[(r0+2)*GPITCH + b0+2] = a22; gs[(r0+2)*GPITCH + b0+3] = a23;
        gs[(r0+3)*GPITCH + b0+0] = a30; gs[(r0+3)*GPITCH + b0+1] = a31;
        gs[(r0+3)*GPITCH + b0+2] = a32; gs[(r0+3)*GPITCH + b0+3] = a33;
    }
    __syncthreads();
    if (team == 0) {
        gs[(r0+0)*GPITCH + b0+0] += a00; gs[(r0+0)*GPITCH + b0+1] += a01;
        gs[(r0+0)*GPITCH + b0+2] += a02; gs[(r0+0)*GPITCH + b0+3] += a03;
        gs[(r0+1)*GPITCH + b0+0] += a10; gs[(r0+1)*GPITCH + b0+1] += a11;
        gs[(r0+1)*GPITCH + b0+2] += a12; gs[(r0+1)*GPITCH + b0+3] += a13;
        gs[(r0+2)*GPITCH + b0+0] += a20; gs[(r0+2)*GPITCH + b0+1] += a21;
        gs[(r0+2)*GPITCH + b0+2] += a22; gs[(r0+2)*GPITCH + b0+3] += a23;
        gs[(r0+3)*GPITCH + b0+0] += a30; gs[(r0+3)*GPITCH + b0+1] += a31;
        gs[(r0+3)*GPITCH + b0+2] += a32; gs[(r0+3)*GPITCH + b0+3] += a33;
    }
    __syncthreads();

    // ---- fused LSTM cell: 512 (jj,b) pairs, 2 per thread ----
#pragma unroll
    for (int q = 0; q < 2; q++) {
        int idx = q * 256 + tid;          // 0..511
        int jj  = idx & 7;
        int b   = idx >> 3;
        int tok = x[b * TT + t];
        const float* tb = g_table + (size_t)tok * GG + j0 + jj;
        float ipre = gs[(0*8 + jj) * GPITCH + b] + tb[0];
        float fpre = gs[(1*8 + jj) * GPITCH + b] + tb[HH];
        float gpre = gs[(2*8 + jj) * GPITCH + b] + tb[2*HH];
        float opre = gs[(3*8 + jj) * GPITCH + b] + tb[3*HH];
        float isg = 1.f / (1.f + expf(-ipre));
        float fsg = 1.f / (1.f + expf(-fpre));
        float gth = tanhf(gpre);
        float osg = 1.f / (1.f + expf(-opre));
        int ci = b * HH + j0 + jj;
        float c = fsg * g_c[ci] + isg * gth;
        g_c[ci] = c;
        hnext[ci] = osg * tanhf(c);
    }
}

// ---------------------------------------------------------------------------
extern "C" void kernel_launch(void* const* d_in, const int* in_sizes, int n_in,
                              void* d_out, int out_size) {
    const int*   x    = (const int*)  d_in[0];
    const float* emb  = (const float*)d_in[1];
    const float* Wih  = (const float*)d_in[2];
    const float* Whh  = (const float*)d_in[3];
    const float* bih  = (const float*)d_in[4];
    const float* bhh  = (const float*)d_in[5];
    const float* h0   = (const float*)d_in[6];
    const float* c0   = (const float*)d_in[7];
    float*       out  = (float*)d_out;

    table_kernel<<<dim3(GG / 128, 256), 128>>>(emb, Wih, bih, bhh);
    initc_kernel<<<(BB * HH) / 256, 256>>>(c0);

    for (int t = 0; t < TT; t++) {
        step_kernel<<<NBLK, 256>>>(Whh, x, h0, out, t);
    }
}